// round 2
// baseline (speedup 1.0000x reference)
#include <cuda_runtime.h>
#include <math.h>

#define H       256
#define NPTS    131072
#define NQ      1000
#define PPC     16          // points per CTA
#define MROWS   (3*PPC)     // 48 logical GEMM rows (h, h', h'')
#define KC      32          // k-chunk staged in smem
#define NTOT    (NPTS + NQ + 2)

// ---------------- device scratch (no allocations allowed) ----------------
__device__ float g_tn[NQ];     // quadrature nodes mapped to [0,1] (fp32)
__device__ float g_qw[NQ];     // quadrature weights (on [-1,1] convention)
__device__ float g_duq[NQ];    // du at quadrature nodes
__device__ float g_u0;
__device__ float g_uL;

// ---------------- Gauss-Legendre nodes/weights (n=1000) -------------------
// Newton on the 3-term recurrence; c1/c2 precomputed so the critical path is
// one FMA per recurrence step.
__global__ void quad_kernel() {
    __shared__ float c1[NQ + 1];
    __shared__ float c2[NQ + 1];
    const int tid = threadIdx.x;
    for (int j = tid + 1; j <= NQ; j += blockDim.x) {
        c1[j] = (2.0f * j - 1.0f) / (float)j;
        c2[j] = ((float)j - 1.0f) / (float)j;
    }
    __syncthreads();

    const int i = blockIdx.x * blockDim.x + tid;   // root pair index 0..499
    if (i >= NQ / 2) return;

    float z = cospif((i + 0.75f) / (NQ + 0.5f));
    float p1 = 1.0f, p2 = 0.0f, pp = 1.0f;
    #pragma unroll 1
    for (int it = 0; it < 6; it++) {
        p1 = 1.0f; p2 = 0.0f;
        #pragma unroll 4
        for (int j = 1; j <= NQ; j++) {
            float p3 = p2;
            p2 = p1;
            p1 = fmaf(c1[j] * z, p2, -(c2[j] * p3));
        }
        pp = (float)NQ * (z * p1 - p2) / (z * z - 1.0f);
        z -= p1 / pp;
    }
    float w = 2.0f / ((1.0f - z * z) * pp * pp);
    // pair (-z, +z); map to [0,1]: t = 0.5*node + 0.5
    g_tn[i]          = 0.5f - 0.5f * z;
    g_tn[NQ - 1 - i] = 0.5f + 0.5f * z;
    g_qw[i]          = w;
    g_qw[NQ - 1 - i] = w;
}

// ---------------- fused MLP forward + 1st/2nd derivative ------------------
struct Smem {
    float A[MROWS][H];    // activation streams  (48*256*4 = 49152 B)
    float W[KC][H];       // weight chunk        (32*256*4 = 32768 B)
    float sv[PPC];        // per-point inputs
    float w4[H];          // final weight vector
};

__global__ __launch_bounds__(256, 2)
void mlp_kernel(const float* __restrict__ x,
                const float* __restrict__ W1, const float* __restrict__ b1,
                const float* __restrict__ W2, const float* __restrict__ b2,
                const float* __restrict__ W3, const float* __restrict__ b3,
                const float* __restrict__ W4, const float* __restrict__ b4,
                float* __restrict__ out)
{
    extern __shared__ unsigned char smem_raw[];
    Smem* sm = (Smem*)smem_raw;

    const int tid = threadIdx.x;
    const int tr  = tid >> 5;   // 0..7  (row group)
    const int tc  = tid & 31;   // 0..31 (col group)
    const int gbase = blockIdx.x * PPC;

    // ---- load point inputs (real points, quad nodes, boundaries, padding)
    if (tid < PPC) {
        int gi = gbase + tid;
        float s;
        if (gi < NPTS)                s = x[gi];
        else if (gi < NPTS + NQ)      s = g_tn[gi - NPTS];
        else if (gi == NPTS + NQ)     s = 0.0f;          // u(0)
        else if (gi == NPTS + NQ + 1) s = 1.0f;          // u(L), L_LEN = 1
        else                          s = 0.0f;          // padding
        sm->sv[tid] = s;
    }
    __syncthreads();

    // ---- layer 1 (elementwise): z1 = s*W1 + b1
    for (int e = tid; e < PPC * H; e += 256) {
        const int p = e >> 8;
        const int n = e & (H - 1);
        const float s  = sm->sv[p];
        const float w  = W1[n];
        const float h  = tanhf(fmaf(s, w, b1[n]));
        const float g  = 1.0f - h * h;
        const float hp = g * w;
        sm->A[p][n]           = h;
        sm->A[PPC + p][n]     = hp;
        sm->A[2 * PPC + p][n] = -2.0f * h * hp * w;
    }

    // ---- two hidden GEMM layers
    const float* Wg_all[2] = {W2, W3};
    const float* bg_all[2] = {b2, b3};

    #pragma unroll 1
    for (int layer = 0; layer < 2; layer++) {
        float acc[6][8];
        #pragma unroll
        for (int i = 0; i < 6; i++)
            #pragma unroll
            for (int j = 0; j < 8; j++) acc[i][j] = 0.0f;

        const float4* Wg = (const float4*)Wg_all[layer];

        #pragma unroll 1
        for (int ch = 0; ch < H / KC; ch++) {
            __syncthreads();
            // stage W chunk: contiguous 8192 floats = 2048 float4
            float4* Wd = (float4*)sm->W;
            #pragma unroll
            for (int r = 0; r < 8; r++)
                Wd[tid + 256 * r] = Wg[ch * 2048 + tid + 256 * r];
            __syncthreads();

            const int kbase = ch * KC;
            #pragma unroll
            for (int k0 = 0; k0 < KC; k0 += 4) {
                float4 a[6];
                #pragma unroll
                for (int i = 0; i < 6; i++)
                    a[i] = *(const float4*)&sm->A[tr + 8 * i][kbase + k0];
                #pragma unroll
                for (int kk = 0; kk < 4; kk++) {
                    const float4 w0 = *(const float4*)&sm->W[k0 + kk][4 * tc];
                    const float4 w1 = *(const float4*)&sm->W[k0 + kk][4 * tc + 128];
                    #pragma unroll
                    for (int i = 0; i < 6; i++) {
                        const float av = (kk == 0) ? a[i].x :
                                         (kk == 1) ? a[i].y :
                                         (kk == 2) ? a[i].z : a[i].w;
                        acc[i][0] = fmaf(av, w0.x, acc[i][0]);
                        acc[i][1] = fmaf(av, w0.y, acc[i][1]);
                        acc[i][2] = fmaf(av, w0.z, acc[i][2]);
                        acc[i][3] = fmaf(av, w0.w, acc[i][3]);
                        acc[i][4] = fmaf(av, w1.x, acc[i][4]);
                        acc[i][5] = fmaf(av, w1.y, acc[i][5]);
                        acc[i][6] = fmaf(av, w1.z, acc[i][6]);
                        acc[i][7] = fmaf(av, w1.w, acc[i][7]);
                    }
                }
            }
        }
        __syncthreads();

        // ---- elementwise tanh-chain, write next activations back to A
        const float* bg = bg_all[layer];
        #pragma unroll
        for (int j = 0; j < 8; j++) {
            const int n = (j < 4) ? (4 * tc + j) : (128 + 4 * tc + (j - 4));
            const float bn = bg[n];
            #pragma unroll
            for (int g2 = 0; g2 < 2; g2++) {
                // rows: tr+8*g2 (h), +16 (h'), +32 (h'')
                const float z   = acc[g2][j] + bn;
                const float zp  = acc[2 + g2][j];
                const float zpp = acc[4 + g2][j];
                const float h   = tanhf(z);
                const float gg  = 1.0f - h * h;
                const float hp  = gg * zp;
                const float hpp = fmaf(gg, zpp, -2.0f * h * hp * zp);
                const int r0 = tr + 8 * g2;
                sm->A[r0][n]      = h;
                sm->A[r0 + 16][n] = hp;
                sm->A[r0 + 32][n] = hpp;
            }
        }
        __syncthreads();
    }

    // ---- final layer: dot with W4 (+ b4 for u only)
    sm->w4[tid] = W4[tid];
    __syncthreads();
    const float b4v = b4[0];

    #pragma unroll
    for (int i = 0; i < 6; i++) {
        const int r = tr + 8 * i;
        float part = 0.0f;
        #pragma unroll
        for (int t = 0; t < 8; t++) {
            const int n = tc + 32 * t;
            part = fmaf(sm->A[r][n], sm->w4[n], part);
        }
        #pragma unroll
        for (int off = 16; off; off >>= 1)
            part += __shfl_down_sync(0xffffffffu, part, off);

        if (tc == 0) {
            const int pt  = r & (PPC - 1);
            const int str = r >> 4;          // 0=u, 1=du, 2=ddu
            const int gi  = gbase + pt;
            if (gi < NPTS) {
                if (str == 0)      out[gi]             = part + b4v;
                else if (str == 1) out[NPTS + gi]      = part;
                else               out[2 * NPTS + gi]  = part;
            } else {
                const int qi = gi - NPTS;
                if (qi < NQ) {
                    if (str == 1) g_duq[qi] = part;
                } else if (qi == NQ) {
                    if (str == 0) g_u0 = part + b4v;
                } else if (qi == NQ + 1) {
                    if (str == 0) g_uL = part + b4v;
                }
            }
        }
    }
}

// ---------------- loss reduction ------------------------------------------
__global__ void loss_kernel(float* __restrict__ out) {
    __shared__ float red[256];
    float s = 0.0f;
    for (int i = threadIdx.x; i < NQ; i += 256) {
        const float d = g_duq[i];
        s = fmaf(g_qw[i] * d, d, s);
    }
    red[threadIdx.x] = s;
    __syncthreads();
    for (int o = 128; o; o >>= 1) {
        if (threadIdx.x < o) red[threadIdx.x] += red[threadIdx.x + o];
        __syncthreads();
    }
    if (threadIdx.x == 0) {
        // EA = 5000*0.0004 = 2 ; inter = 0.5*EA*0.5*(b-a)*S = 0.5*S
        const float inter = 0.5f * red[0];
        const float loss  = (inter - 5.0f * g_uL) + g_u0 * g_u0;
        out[3 * NPTS] = loss;
    }
}

// ---------------- launch ---------------------------------------------------
extern "C" void kernel_launch(void* const* d_in, const int* in_sizes, int n_in,
                              void* d_out, int out_size)
{
    const float* x  = (const float*)d_in[0];
    const float* W1 = (const float*)d_in[1];
    const float* b1 = (const float*)d_in[2];
    const float* W2 = (const float*)d_in[3];
    const float* b2 = (const float*)d_in[4];
    const float* W3 = (const float*)d_in[5];
    const float* b3 = (const float*)d_in[6];
    const float* W4 = (const float*)d_in[7];
    const float* b4 = (const float*)d_in[8];
    float* out = (float*)d_out;

    const int smem_bytes = (int)sizeof(Smem);
    cudaFuncSetAttribute(mlp_kernel,
                         cudaFuncAttributeMaxDynamicSharedMemorySize, smem_bytes);

    quad_kernel<<<8, 64>>>();

    const int nblocks = (NTOT + PPC - 1) / PPC;
    mlp_kernel<<<nblocks, 256, smem_bytes>>>(x, W1, b1, W2, b2, W3, b3, W4, b4, out);

    loss_kernel<<<1, 256>>>(out);
}

// round 3
// speedup vs baseline: 1.0001x; 1.0001x over previous
#include <cuda_runtime.h>
#include <math.h>

#define H       256
#define NPTS    131072
#define NQ      1000
#define PPC     16          // points per CTA
#define MROWS   (3*PPC)     // 48 logical GEMM rows (h, h', h'')
#define KC      32          // k-chunk staged in smem
#define NTOT    (NPTS + NQ + 2)

// ---------------- device scratch (no allocations allowed) ----------------
__device__ float g_tn[NQ];     // quadrature nodes mapped to [0,1] (fp32)
__device__ float g_qw[NQ];     // quadrature weights (on [-1,1] convention)
__device__ float g_duq[NQ];    // du at quadrature nodes
__device__ float g_u0;
__device__ float g_uL;

// ---------------- Gauss-Legendre nodes/weights (n=1000) -------------------
// Newton on the 3-term recurrence; c1/c2 precomputed so the critical path is
// one FMA per recurrence step.
__global__ void quad_kernel() {
    __shared__ float c1[NQ + 1];
    __shared__ float c2[NQ + 1];
    const int tid = threadIdx.x;
    for (int j = tid + 1; j <= NQ; j += blockDim.x) {
        c1[j] = (2.0f * j - 1.0f) / (float)j;
        c2[j] = ((float)j - 1.0f) / (float)j;
    }
    __syncthreads();

    const int i = blockIdx.x * blockDim.x + tid;   // root pair index 0..499
    if (i >= NQ / 2) return;

    float z = cospif((i + 0.75f) / (NQ + 0.5f));
    float p1 = 1.0f, p2 = 0.0f, pp = 1.0f;
    #pragma unroll 1
    for (int it = 0; it < 6; it++) {
        p1 = 1.0f; p2 = 0.0f;
        #pragma unroll 4
        for (int j = 1; j <= NQ; j++) {
            float p3 = p2;
            p2 = p1;
            p1 = fmaf(c1[j] * z, p2, -(c2[j] * p3));
        }
        pp = (float)NQ * (z * p1 - p2) / (z * z - 1.0f);
        z -= p1 / pp;
    }
    float w = 2.0f / ((1.0f - z * z) * pp * pp);
    // pair (-z, +z); map to [0,1]: t = 0.5*node + 0.5
    g_tn[i]          = 0.5f - 0.5f * z;
    g_tn[NQ - 1 - i] = 0.5f + 0.5f * z;
    g_qw[i]          = w;
    g_qw[NQ - 1 - i] = w;
}

// ---------------- fused MLP forward + 1st/2nd derivative ------------------
struct Smem {
    float A[MROWS][H];    // activation streams  (48*256*4 = 49152 B)
    float W[KC][H];       // weight chunk        (32*256*4 = 32768 B)
    float sv[PPC];        // per-point inputs
    float w4[H];          // final weight vector
};

__global__ __launch_bounds__(256, 2)
void mlp_kernel(const float* __restrict__ x,
                const float* __restrict__ W1, const float* __restrict__ b1,
                const float* __restrict__ W2, const float* __restrict__ b2,
                const float* __restrict__ W3, const float* __restrict__ b3,
                const float* __restrict__ W4, const float* __restrict__ b4,
                float* __restrict__ out)
{
    extern __shared__ unsigned char smem_raw[];
    Smem* sm = (Smem*)smem_raw;

    const int tid = threadIdx.x;
    const int tr  = tid >> 5;   // 0..7  (row group)
    const int tc  = tid & 31;   // 0..31 (col group)
    const int gbase = blockIdx.x * PPC;

    // ---- load point inputs (real points, quad nodes, boundaries, padding)
    if (tid < PPC) {
        int gi = gbase + tid;
        float s;
        if (gi < NPTS)                s = x[gi];
        else if (gi < NPTS + NQ)      s = g_tn[gi - NPTS];
        else if (gi == NPTS + NQ)     s = 0.0f;          // u(0)
        else if (gi == NPTS + NQ + 1) s = 1.0f;          // u(L), L_LEN = 1
        else                          s = 0.0f;          // padding
        sm->sv[tid] = s;
    }
    __syncthreads();

    // ---- layer 1 (elementwise): z1 = s*W1 + b1
    for (int e = tid; e < PPC * H; e += 256) {
        const int p = e >> 8;
        const int n = e & (H - 1);
        const float s  = sm->sv[p];
        const float w  = W1[n];
        const float h  = tanhf(fmaf(s, w, b1[n]));
        const float g  = 1.0f - h * h;
        const float hp = g * w;
        sm->A[p][n]           = h;
        sm->A[PPC + p][n]     = hp;
        sm->A[2 * PPC + p][n] = -2.0f * h * hp * w;
    }

    // ---- two hidden GEMM layers
    const float* Wg_all[2] = {W2, W3};
    const float* bg_all[2] = {b2, b3};

    #pragma unroll 1
    for (int layer = 0; layer < 2; layer++) {
        float acc[6][8];
        #pragma unroll
        for (int i = 0; i < 6; i++)
            #pragma unroll
            for (int j = 0; j < 8; j++) acc[i][j] = 0.0f;

        const float4* Wg = (const float4*)Wg_all[layer];

        #pragma unroll 1
        for (int ch = 0; ch < H / KC; ch++) {
            __syncthreads();
            // stage W chunk: contiguous 8192 floats = 2048 float4
            float4* Wd = (float4*)sm->W;
            #pragma unroll
            for (int r = 0; r < 8; r++)
                Wd[tid + 256 * r] = Wg[ch * 2048 + tid + 256 * r];
            __syncthreads();

            const int kbase = ch * KC;
            #pragma unroll
            for (int k0 = 0; k0 < KC; k0 += 4) {
                float4 a[6];
                #pragma unroll
                for (int i = 0; i < 6; i++)
                    a[i] = *(const float4*)&sm->A[tr + 8 * i][kbase + k0];
                #pragma unroll
                for (int kk = 0; kk < 4; kk++) {
                    const float4 w0 = *(const float4*)&sm->W[k0 + kk][4 * tc];
                    const float4 w1 = *(const float4*)&sm->W[k0 + kk][4 * tc + 128];
                    #pragma unroll
                    for (int i = 0; i < 6; i++) {
                        const float av = (kk == 0) ? a[i].x :
                                         (kk == 1) ? a[i].y :
                                         (kk == 2) ? a[i].z : a[i].w;
                        acc[i][0] = fmaf(av, w0.x, acc[i][0]);
                        acc[i][1] = fmaf(av, w0.y, acc[i][1]);
                        acc[i][2] = fmaf(av, w0.z, acc[i][2]);
                        acc[i][3] = fmaf(av, w0.w, acc[i][3]);
                        acc[i][4] = fmaf(av, w1.x, acc[i][4]);
                        acc[i][5] = fmaf(av, w1.y, acc[i][5]);
                        acc[i][6] = fmaf(av, w1.z, acc[i][6]);
                        acc[i][7] = fmaf(av, w1.w, acc[i][7]);
                    }
                }
            }
        }
        __syncthreads();

        // ---- elementwise tanh-chain, write next activations back to A
        const float* bg = bg_all[layer];
        #pragma unroll
        for (int j = 0; j < 8; j++) {
            const int n = (j < 4) ? (4 * tc + j) : (128 + 4 * tc + (j - 4));
            const float bn = bg[n];
            #pragma unroll
            for (int g2 = 0; g2 < 2; g2++) {
                // rows: tr+8*g2 (h), +16 (h'), +32 (h'')
                const float z   = acc[g2][j] + bn;
                const float zp  = acc[2 + g2][j];
                const float zpp = acc[4 + g2][j];
                const float h   = tanhf(z);
                const float gg  = 1.0f - h * h;
                const float hp  = gg * zp;
                const float hpp = fmaf(gg, zpp, -2.0f * h * hp * zp);
                const int r0 = tr + 8 * g2;
                sm->A[r0][n]      = h;
                sm->A[r0 + 16][n] = hp;
                sm->A[r0 + 32][n] = hpp;
            }
        }
        __syncthreads();
    }

    // ---- final layer: dot with W4 (+ b4 for u only)
    sm->w4[tid] = W4[tid];
    __syncthreads();
    const float b4v = b4[0];

    #pragma unroll
    for (int i = 0; i < 6; i++) {
        const int r = tr + 8 * i;
        float part = 0.0f;
        #pragma unroll
        for (int t = 0; t < 8; t++) {
            const int n = tc + 32 * t;
            part = fmaf(sm->A[r][n], sm->w4[n], part);
        }
        #pragma unroll
        for (int off = 16; off; off >>= 1)
            part += __shfl_down_sync(0xffffffffu, part, off);

        if (tc == 0) {
            const int pt  = r & (PPC - 1);
            const int str = r >> 4;          // 0=u, 1=du, 2=ddu
            const int gi  = gbase + pt;
            if (gi < NPTS) {
                if (str == 0)      out[gi]             = part + b4v;
                else if (str == 1) out[NPTS + gi]      = part;
                else               out[2 * NPTS + gi]  = part;
            } else {
                const int qi = gi - NPTS;
                if (qi < NQ) {
                    if (str == 1) g_duq[qi] = part;
                } else if (qi == NQ) {
                    if (str == 0) g_u0 = part + b4v;
                } else if (qi == NQ + 1) {
                    if (str == 0) g_uL = part + b4v;
                }
            }
        }
    }
}

// ---------------- loss reduction ------------------------------------------
__global__ void loss_kernel(float* __restrict__ out) {
    __shared__ float red[256];
    float s = 0.0f;
    for (int i = threadIdx.x; i < NQ; i += 256) {
        const float d = g_duq[i];
        s = fmaf(g_qw[i] * d, d, s);
    }
    red[threadIdx.x] = s;
    __syncthreads();
    for (int o = 128; o; o >>= 1) {
        if (threadIdx.x < o) red[threadIdx.x] += red[threadIdx.x + o];
        __syncthreads();
    }
    if (threadIdx.x == 0) {
        // EA = 5000*0.0004 = 2 ; inter = 0.5*EA*0.5*(b-a)*S = 0.5*S
        const float inter = 0.5f * red[0];
        const float loss  = (inter - 5.0f * g_uL) + g_u0 * g_u0;
        out[3 * NPTS] = loss;
    }
}

// ---------------- launch ---------------------------------------------------
extern "C" void kernel_launch(void* const* d_in, const int* in_sizes, int n_in,
                              void* d_out, int out_size)
{
    const float* x  = (const float*)d_in[0];
    const float* W1 = (const float*)d_in[1];
    const float* b1 = (const float*)d_in[2];
    const float* W2 = (const float*)d_in[3];
    const float* b2 = (const float*)d_in[4];
    const float* W3 = (const float*)d_in[5];
    const float* b3 = (const float*)d_in[6];
    const float* W4 = (const float*)d_in[7];
    const float* b4 = (const float*)d_in[8];
    float* out = (float*)d_out;

    const int smem_bytes = (int)sizeof(Smem);
    cudaFuncSetAttribute(mlp_kernel,
                         cudaFuncAttributeMaxDynamicSharedMemorySize, smem_bytes);

    quad_kernel<<<8, 64>>>();

    const int nblocks = (NTOT + PPC - 1) / PPC;
    mlp_kernel<<<nblocks, 256, smem_bytes>>>(x, W1, b1, W2, b2, W3, b3, W4, b4, out);

    loss_kernel<<<1, 256>>>(out);
}

// round 5
// speedup vs baseline: 1.9998x; 1.9996x over previous
#include <cuda_runtime.h>
#include <cuda_bf16.h>
#include <math.h>

#define NPTS 131072
#define NQ   1000
#define PPC  32
#define NTOT (NPTS + NQ + 2)
#define NTILES  4128
#define NQTILES 32
#define ROWP 528                      // bytes per smem matrix row (264 bf16)

// smem byte offsets
#define SA_HI 0                       // A hi  [96][264] bf16 = 50688
#define SA_LO 50688
#define SB_HI 101376                  // B chunk hi [64][264] bf16 = 33792
#define SB_LO 135168
#define SBIAS 168960
#define SW4   169984
#define SSV   171008
#define SDRED 171136                  // [3][32][8] f32 = 3072
#define SM_ALLOC 174336

__device__ float g_qw[NQ];
__device__ float g_duq[NQ];
__device__ float g_u0, g_uL;
__device__ __nv_bfloat16 g_Bh[2][256][256];   // [layer][n][k] = W[k][n] hi
__device__ __nv_bfloat16 g_Bl[2][256][256];   // lo residual

// ---------------- mma.sync helpers (baseline PTX, sm_80+) ----------------
__device__ __forceinline__ void ldsm4(unsigned& r0, unsigned& r1, unsigned& r2,
                                      unsigned& r3, unsigned addr) {
    asm volatile("ldmatrix.sync.aligned.m8n8.x4.shared.b16 {%0,%1,%2,%3}, [%4];"
                 : "=r"(r0), "=r"(r1), "=r"(r2), "=r"(r3) : "r"(addr));
}
__device__ __forceinline__ void ldsm2(unsigned& r0, unsigned& r1, unsigned addr) {
    asm volatile("ldmatrix.sync.aligned.m8n8.x2.shared.b16 {%0,%1}, [%2];"
                 : "=r"(r0), "=r"(r1) : "r"(addr));
}
__device__ __forceinline__ void mma16816(float* c, const unsigned* a,
                                         unsigned b0, unsigned b1) {
    asm volatile(
        "mma.sync.aligned.m16n8k16.row.col.f32.bf16.bf16.f32 "
        "{%0,%1,%2,%3}, {%4,%5,%6,%7}, {%8,%9}, {%0,%1,%2,%3};"
        : "+f"(c[0]), "+f"(c[1]), "+f"(c[2]), "+f"(c[3])
        : "r"(a[0]), "r"(a[1]), "r"(a[2]), "r"(a[3]), "r"(b0), "r"(b1));
}
__device__ __forceinline__ unsigned pack_bf16_pair(float a, float b) {
    __nv_bfloat162 t = __floats2bfloat162_rn(a, b);
    return *(unsigned*)&t;
}
// store split-bf16 pair (k even) for a row into A hi/lo
__device__ __forceinline__ void store_A_pair(char* gb, int row, int k, float v0, float v1) {
    float h0 = __bfloat162float(__float2bfloat16_rn(v0));
    float h1 = __bfloat162float(__float2bfloat16_rn(v1));
    unsigned off = (unsigned)row * ROWP + (unsigned)k * 2;
    *(unsigned*)(gb + SA_HI + off) = pack_bf16_pair(v0, v1);
    *(unsigned*)(gb + SA_LO + off) = pack_bf16_pair(v0 - h0, v1 - h1);
}

// ---------------- prep: W2/W3 -> transposed hi/lo bf16 [n][k] ----------------
__global__ void prep_kernel(const float* __restrict__ W2, const float* __restrict__ W3) {
    int idx = blockIdx.x * 256 + threadIdx.x;   // 131072 = (l, k, n)
    int l = idx >> 16;
    int r = idx & 65535;
    int k = r >> 8;
    int n = r & 255;
    float v = (l ? W3 : W2)[k * 256 + n];
    __nv_bfloat16 h = __float2bfloat16_rn(v);
    g_Bh[l][n][k] = h;
    g_Bl[l][n][k] = __float2bfloat16_rn(v - __bfloat162float(h));
}

// ---------------- fused MLP + derivatives ----------------
__global__ __launch_bounds__(256, 1)
void mlp_kernel(const float* __restrict__ x,
                const float* __restrict__ W1, const float* __restrict__ b1,
                const float* __restrict__ b2, const float* __restrict__ b3,
                const float* __restrict__ W4, const float* __restrict__ b4,
                float* __restrict__ out)
{
    extern __shared__ unsigned char smraw[];
    char* gb = (char*)smraw;
    unsigned sb = (unsigned)__cvta_generic_to_shared(smraw);

    const int tid  = threadIdx.x;
    const int w    = tid >> 5;
    const int lane = tid & 31;
    const int bid  = blockIdx.x;
    const int tile  = (bid < NQTILES) ? (NTILES - NQTILES + bid) : (bid - NQTILES);
    const int gbase = tile * PPC;

    ((float*)(gb + SW4))[tid] = W4[tid];
    const float b4v = b4[0];

    // ---- point inputs; quad tiles run Newton root-finding in-CTA ----
    float sval = 0.0f;
    if (tid < PPC) {
        int gi = gbase + tid;
        if (gi < NPTS)                sval = x[gi];
        else if (gi == NPTS + NQ + 1) sval = 1.0f;     // u(L)
    }
    if (bid < NQTILES) {
        float* c1 = (float*)(gb + SB_HI);
        float* c2 = (float*)(gb + SB_LO);
        for (int j = tid + 1; j <= NQ; j += 256) {
            c1[j] = (2.0f * j - 1.0f) / (float)j;
            c2[j] = ((float)j - 1.0f) / (float)j;
        }
        __syncthreads();
        if (tid < PPC) {
            int qi = bid * PPC + tid;
            if (qi < NQ) {
                float z = cospif((qi + 0.75f) / (NQ + 0.5f));
                float p1 = 1.0f, p2 = 0.0f, pp = 1.0f;
                #pragma unroll 1
                for (int it = 0; it < 4; it++) {
                    p1 = 1.0f; p2 = 0.0f;
                    #pragma unroll 4
                    for (int j = 1; j <= NQ; j++) {
                        float p3 = p2; p2 = p1;
                        p1 = fmaf(c1[j] * z, p2, -(c2[j] * p3));
                    }
                    pp = (float)NQ * (z * p1 - p2) / (z * z - 1.0f);
                    z -= p1 / pp;
                }
                g_qw[qi] = 2.0f / ((1.0f - z * z) * pp * pp);
                sval = 0.5f * z + 0.5f;
            }
        }
        __syncthreads();
    }
    if (tid < PPC) ((float*)(gb + SSV))[tid] = sval;
    __syncthreads();

    // ---- layer-1 seeds: rows p (h), 32+p (h'), 64+p (h'') ----
    {
        const float* sv = (const float*)(gb + SSV);
        for (int e = tid; e < PPC * 128; e += 256) {
            int p = e >> 7;
            int k = (e & 127) * 2;
            float s = sv[p];
            float2 wv = *(const float2*)&W1[k];
            float2 bv = *(const float2*)&b1[k];
            float h0 = tanhf(fmaf(s, wv.x, bv.x));
            float h1 = tanhf(fmaf(s, wv.y, bv.y));
            float g0 = 1.0f - h0 * h0, g1 = 1.0f - h1 * h1;
            float hp0 = g0 * wv.x, hp1 = g1 * wv.y;
            store_A_pair(gb, p,      k, h0, h1);
            store_A_pair(gb, 32 + p, k, hp0, hp1);
            store_A_pair(gb, 64 + p, k, -2.0f * h0 * hp0 * wv.x, -2.0f * h1 * hp1 * wv.y);
        }
    }

    // per-lane ldmatrix base addresses
    const unsigned aA = sb + SA_HI
        + (unsigned)(((lane >> 3) & 1) * 8 + (lane & 7)) * ROWP
        + (unsigned)((lane >> 4) << 3) * 2;
    const unsigned aB = sb + SB_HI
        + (unsigned)(w * 8 + (lane & 7)) * ROWP
        + (unsigned)(((lane >> 3) & 1) * 8) * 2;

    #pragma unroll 1
    for (int l = 0; l < 2; l++) {
        ((float*)(gb + SBIAS))[tid] = (l ? b3 : b2)[tid];
        float acc[24][4];
        #pragma unroll
        for (int i = 0; i < 24; i++)
            #pragma unroll
            for (int j = 0; j < 4; j++) acc[i][j] = 0.0f;

        #pragma unroll
        for (int nc = 0; nc < 4; nc++) {
            __syncthreads();
            {   // stage B chunk hi+lo: 64 n-rows x 256 k
                const uint4* srcH = (const uint4*)&g_Bh[l][nc * 64][0];
                const uint4* srcL = (const uint4*)&g_Bl[l][nc * 64][0];
                #pragma unroll
                for (int i = 0; i < 8; i++) {
                    int idx = tid + 256 * i;
                    int row = idx >> 5, q = idx & 31;
                    *(uint4*)(gb + SB_HI + row * ROWP + q * 16) = srcH[idx];
                    *(uint4*)(gb + SB_LO + row * ROWP + q * 16) = srcL[idx];
                }
            }
            __syncthreads();

            #pragma unroll 2
            for (int ks = 0; ks < 16; ks++) {
                unsigned bh0, bh1, bl0, bl1;
                ldsm2(bh0, bh1, aB + ks * 32);
                ldsm2(bl0, bl1, aB + (SB_LO - SB_HI) + ks * 32);
                unsigned ah[6][4], al[6][4];
                #pragma unroll
                for (int m = 0; m < 6; m++) {
                    ldsm4(ah[m][0], ah[m][1], ah[m][2], ah[m][3],
                          aA + m * 16 * ROWP + ks * 32);
                    ldsm4(al[m][0], al[m][1], al[m][2], al[m][3],
                          aA + (SA_LO - SA_HI) + m * 16 * ROWP + ks * 32);
                }
                #pragma unroll
                for (int m = 0; m < 6; m++) mma16816(acc[m * 4 + nc], ah[m], bh0, bh1);
                #pragma unroll
                for (int m = 0; m < 6; m++) mma16816(acc[m * 4 + nc], ah[m], bl0, bl1);
                #pragma unroll
                for (int m = 0; m < 6; m++) mma16816(acc[m * 4 + nc], al[m], bh0, bh1);
            }
        }
        __syncthreads();   // all A reads done before epilogue overwrites A

        const float* bias = (const float*)(gb + SBIAS);
        const float* w4s  = (const float*)(gb + SW4);

        if (l == 0) {
            // tanh-chain coupling entirely in registers; write next-layer A
            #pragma unroll
            for (int g = 0; g < 2; g++)
                #pragma unroll
                for (int nc = 0; nc < 4; nc++) {
                    const float* zA = acc[g * 4 + nc];
                    const float* zP = acc[(2 + g) * 4 + nc];
                    const float* zQ = acc[(4 + g) * 4 + nc];
                    int n0 = nc * 64 + w * 8 + (lane & 3) * 2;
                    float bb0 = bias[n0], bb1 = bias[n0 + 1];
                    #pragma unroll
                    for (int rh = 0; rh < 2; rh++) {
                        int row = g * 16 + rh * 8 + (lane >> 2);
                        float h0 = tanhf(zA[rh * 2] + bb0);
                        float h1 = tanhf(zA[rh * 2 + 1] + bb1);
                        float g0 = 1.0f - h0 * h0, g1 = 1.0f - h1 * h1;
                        float hp0 = g0 * zP[rh * 2], hp1 = g1 * zP[rh * 2 + 1];
                        float hq0 = fmaf(g0, zQ[rh * 2],     -2.0f * h0 * hp0 * zP[rh * 2]);
                        float hq1 = fmaf(g1, zQ[rh * 2 + 1], -2.0f * h1 * hp1 * zP[rh * 2 + 1]);
                        store_A_pair(gb, row,      n0, h0, h1);
                        store_A_pair(gb, 32 + row, n0, hp0, hp1);
                        store_A_pair(gb, 64 + row, n0, hq0, hq1);
                    }
                }
        } else {
            // final tanh + dot with W4
            float uu[2][2]  = {{0, 0}, {0, 0}};
            float du_[2][2] = {{0, 0}, {0, 0}};
            float dd_[2][2] = {{0, 0}, {0, 0}};
            #pragma unroll
            for (int g = 0; g < 2; g++)
                #pragma unroll
                for (int nc = 0; nc < 4; nc++) {
                    const float* zA = acc[g * 4 + nc];
                    const float* zP = acc[(2 + g) * 4 + nc];
                    const float* zQ = acc[(4 + g) * 4 + nc];
                    int n0 = nc * 64 + w * 8 + (lane & 3) * 2;
                    float bb0 = bias[n0], bb1 = bias[n0 + 1];
                    float w40 = w4s[n0], w41 = w4s[n0 + 1];
                    #pragma unroll
                    for (int rh = 0; rh < 2; rh++) {
                        float h0 = tanhf(zA[rh * 2] + bb0);
                        float h1 = tanhf(zA[rh * 2 + 1] + bb1);
                        float g0 = 1.0f - h0 * h0, g1 = 1.0f - h1 * h1;
                        float hp0 = g0 * zP[rh * 2], hp1 = g1 * zP[rh * 2 + 1];
                        float hq0 = fmaf(g0, zQ[rh * 2],     -2.0f * h0 * hp0 * zP[rh * 2]);
                        float hq1 = fmaf(g1, zQ[rh * 2 + 1], -2.0f * h1 * hp1 * zP[rh * 2 + 1]);
                        uu[g][rh]  += h0  * w40 + h1  * w41;
                        du_[g][rh] += hp0 * w40 + hp1 * w41;
                        dd_[g][rh] += hq0 * w40 + hq1 * w41;
                    }
                }
            float* dred = (float*)(gb + SDRED);
            #pragma unroll
            for (int g = 0; g < 2; g++)
                #pragma unroll
                for (int rh = 0; rh < 2; rh++) {
                    float a = uu[g][rh], b = du_[g][rh], c = dd_[g][rh];
                    a += __shfl_xor_sync(0xffffffffu, a, 1);
                    a += __shfl_xor_sync(0xffffffffu, a, 2);
                    b += __shfl_xor_sync(0xffffffffu, b, 1);
                    b += __shfl_xor_sync(0xffffffffu, b, 2);
                    c += __shfl_xor_sync(0xffffffffu, c, 1);
                    c += __shfl_xor_sync(0xffffffffu, c, 2);
                    if ((lane & 3) == 0) {
                        int p = g * 16 + rh * 8 + (lane >> 2);
                        dred[(0 * 32 + p) * 8 + w] = a;
                        dred[(1 * 32 + p) * 8 + w] = b;
                        dred[(2 * 32 + p) * 8 + w] = c;
                    }
                }
            __syncthreads();
            if (w < 3) {
                const float* dr = (const float*)(gb + SDRED) + (w * 32 + lane) * 8;
                float v = 0.0f;
                #pragma unroll
                for (int i = 0; i < 8; i++) v += dr[i];
                int gi = gbase + lane;
                if (w == 0) {
                    v += b4v;
                    if (gi < NPTS) out[gi] = v;
                    else {
                        int qi = gi - NPTS;
                        if (qi == NQ)          g_u0 = v;
                        else if (qi == NQ + 1) g_uL = v;
                    }
                } else if (w == 1) {
                    if (gi < NPTS) out[NPTS + gi] = v;
                    else { int qi = gi - NPTS; if (qi < NQ) g_duq[qi] = v; }
                } else {
                    if (gi < NPTS) out[2 * NPTS + gi] = v;
                }
            }
        }
    }
}

// ---------------- loss reduction ----------------
__global__ void loss_kernel(float* __restrict__ out) {
    __shared__ float red[256];
    float sacc = 0.0f;
    for (int i = threadIdx.x; i < NQ; i += 256) {
        const float d = g_duq[i];
        sacc = fmaf(g_qw[i] * d, d, sacc);
    }
    red[threadIdx.x] = sacc;
    __syncthreads();
    for (int o = 128; o; o >>= 1) {
        if (threadIdx.x < o) red[threadIdx.x] += red[threadIdx.x + o];
        __syncthreads();
    }
    if (threadIdx.x == 0)
        out[3 * NPTS] = (0.5f * red[0] - 5.0f * g_uL) + g_u0 * g_u0;
}

// ---------------- launch ----------------
extern "C" void kernel_launch(void* const* d_in, const int* in_sizes, int n_in,
                              void* d_out, int out_size)
{
    (void)in_sizes; (void)n_in; (void)out_size;
    const float* x  = (const float*)d_in[0];
    const float* W1 = (const float*)d_in[1];
    const float* b1 = (const float*)d_in[2];
    const float* W2 = (const float*)d_in[3];
    const float* b2 = (const float*)d_in[4];
    const float* W3 = (const float*)d_in[5];
    const float* b3 = (const float*)d_in[6];
    const float* W4 = (const float*)d_in[7];
    const float* b4 = (const float*)d_in[8];
    float* out = (float*)d_out;

    cudaFuncSetAttribute(mlp_kernel,
                         cudaFuncAttributeMaxDynamicSharedMemorySize, SM_ALLOC);

    prep_kernel<<<512, 256>>>(W2, W3);
    mlp_kernel<<<NTILES, 256, SM_ALLOC>>>(x, W1, b1, b2, b3, W4, b4, out);
    loss_kernel<<<1, 256>>>(out);
}

// round 6
// speedup vs baseline: 2.9498x; 1.4751x over previous
#include <cuda_runtime.h>
#include <cuda_bf16.h>
#include <math.h>

#define NPTS 131072
#define NQ   1000
#define PPC  32
#define NTOT (NPTS + NQ + 2)
#define NTILES  4128
#define NQTILES 32
#define ROWP 528                 // bytes per A smem row (264 bf16)

// smem map (A hi/lo only; B comes straight from L2 in fragment order)
#define SA_HI 0                  // [96][264] bf16 = 50688
#define SA_LO 50688
#define SBIAS 101376
#define SW4   102400
#define SSV   103424
#define SDRED 103680             // [3][32][4] f32 = 1536
#define SM_ALLOC 105472

__device__ float g_qw[NQ];
__device__ float g_duq[NQ];
__device__ float g_u0, g_uL;
// B in mma-fragment order: [layer][split][nc][wgn][ks][lane] -> uint4 = 4 b16x2 regs
__device__ uint4 g_Bf[2][2][4][4][16][32];

// ---------------- mma.sync helpers (baseline PTX, sm_80+) ----------------
__device__ __forceinline__ void ldsm4(unsigned& r0, unsigned& r1, unsigned& r2,
                                      unsigned& r3, unsigned addr) {
    asm volatile("ldmatrix.sync.aligned.m8n8.x4.shared.b16 {%0,%1,%2,%3}, [%4];"
                 : "=r"(r0), "=r"(r1), "=r"(r2), "=r"(r3) : "r"(addr));
}
__device__ __forceinline__ void mma16816(float* c, const unsigned* a,
                                         unsigned b0, unsigned b1) {
    asm volatile(
        "mma.sync.aligned.m16n8k16.row.col.f32.bf16.bf16.f32 "
        "{%0,%1,%2,%3}, {%4,%5,%6,%7}, {%8,%9}, {%0,%1,%2,%3};"
        : "+f"(c[0]), "+f"(c[1]), "+f"(c[2]), "+f"(c[3])
        : "r"(a[0]), "r"(a[1]), "r"(a[2]), "r"(a[3]), "r"(b0), "r"(b1));
}
__device__ __forceinline__ unsigned pack_bf16_pair(float a, float b) {
    __nv_bfloat162 t = __floats2bfloat162_rn(a, b);
    return *(unsigned*)&t;
}
__device__ __forceinline__ void store_A_pair(char* gb, int row, int k, float v0, float v1) {
    float h0 = __bfloat162float(__float2bfloat16_rn(v0));
    float h1 = __bfloat162float(__float2bfloat16_rn(v1));
    unsigned off = (unsigned)row * ROWP + (unsigned)k * 2;
    *(unsigned*)(gb + SA_HI + off) = pack_bf16_pair(v0, v1);
    *(unsigned*)(gb + SA_LO + off) = pack_bf16_pair(v0 - h0, v1 - h1);
}

// ---------------- prep: W2/W3 -> hi/lo bf16 fragments in mma order ----------
__global__ void prep_kernel(const float* __restrict__ W2, const float* __restrict__ W3) {
    int idx = blockIdx.x * 256 + threadIdx.x;      // 32768 uint4
    int lane = idx & 31;  int t = idx >> 5;
    int ks  = t & 15; t >>= 4;
    int wgn = t & 3;  t >>= 2;
    int nc  = t & 3;  t >>= 2;
    int split = t & 1;
    int l = t >> 1;
    const float* W = l ? W3 : W2;
    unsigned r[4];
    #pragma unroll
    for (int n8 = 0; n8 < 2; n8++)
        #pragma unroll
        for (int kb = 0; kb < 2; kb++) {
            int n = nc * 64 + wgn * 16 + n8 * 8 + (lane >> 2);
            int k = ks * 16 + kb * 8 + (lane & 3) * 2;
            float v0 = W[k * 256 + n];
            float v1 = W[(k + 1) * 256 + n];
            if (!split) {
                r[n8 * 2 + kb] = pack_bf16_pair(v0, v1);
            } else {
                float h0 = __bfloat162float(__float2bfloat16_rn(v0));
                float h1 = __bfloat162float(__float2bfloat16_rn(v1));
                r[n8 * 2 + kb] = pack_bf16_pair(v0 - h0, v1 - h1);
            }
        }
    g_Bf[l][split][nc][wgn][ks][lane] = make_uint4(r[0], r[1], r[2], r[3]);
}

// ---------------- fused MLP + 1st/2nd derivative ----------------
__global__ __launch_bounds__(256, 1)
void mlp_kernel(const float* __restrict__ x,
                const float* __restrict__ W1, const float* __restrict__ b1,
                const float* __restrict__ b2, const float* __restrict__ b3,
                const float* __restrict__ W4, const float* __restrict__ b4,
                float* __restrict__ out)
{
    extern __shared__ unsigned char smraw[];
    char* gb = (char*)smraw;
    unsigned sb = (unsigned)__cvta_generic_to_shared(smraw);

    const int tid  = threadIdx.x;
    const int w    = tid >> 5;
    const int lane = tid & 31;
    const int wgm  = w >> 2;      // 0..1 : which 16-point half
    const int wgn  = w & 3;       // 0..3 : 16-col group within 64-col chunk
    const int bid  = blockIdx.x;
    const int tile  = (bid < NQTILES) ? (NTILES - NQTILES + bid) : (bid - NQTILES);
    const int gbase = tile * PPC;

    ((float*)(gb + SW4))[tid] = W4[tid];
    const float b4v = b4[0];

    // ---- point inputs; quad tiles do Gauss-Legendre Newton in-CTA ----
    float sval = 0.0f;
    if (tid < PPC) {
        int gi = gbase + tid;
        if (gi < NPTS)                sval = x[gi];
        else if (gi == NPTS + NQ + 1) sval = 1.0f;      // u(L)
    }
    if (bid < NQTILES) {
        float* c1 = (float*)(gb + 0);        // scratch in A region (pre-seed)
        float* c2 = (float*)(gb + 4096);
        for (int j = tid + 1; j <= NQ; j += 256) {
            c1[j] = (2.0f * j - 1.0f) / (float)j;
            c2[j] = ((float)j - 1.0f) / (float)j;
        }
        __syncthreads();
        if (tid < PPC) {
            int qi = bid * PPC + tid;
            if (qi < NQ) {
                float z = cospif((qi + 0.75f) / (NQ + 0.5f));
                float p1 = 1.0f, p2 = 0.0f, pp = 1.0f;
                #pragma unroll 1
                for (int it = 0; it < 4; it++) {
                    p1 = 1.0f; p2 = 0.0f;
                    #pragma unroll 4
                    for (int j = 1; j <= NQ; j++) {
                        float p3 = p2; p2 = p1;
                        p1 = fmaf(c1[j] * z, p2, -(c2[j] * p3));
                    }
                    pp = (float)NQ * (z * p1 - p2) / (z * z - 1.0f);
                    z -= p1 / pp;
                }
                g_qw[qi] = 2.0f / ((1.0f - z * z) * pp * pp);
                sval = 0.5f * z + 0.5f;
            }
        }
        __syncthreads();
    }
    if (tid < PPC) ((float*)(gb + SSV))[tid] = sval;
    __syncthreads();

    // ---- layer-1 seeds: rows p (h), 32+p (h'), 64+p (h'') -- all 96 rows ----
    {
        const float* sv = (const float*)(gb + SSV);
        for (int e = tid; e < PPC * 128; e += 256) {
            int p = e >> 7;
            int k = (e & 127) * 2;
            float s = sv[p];
            float2 wv = *(const float2*)&W1[k];
            float2 bv = *(const float2*)&b1[k];
            float h0 = tanhf(fmaf(s, wv.x, bv.x));
            float h1 = tanhf(fmaf(s, wv.y, bv.y));
            float g0 = 1.0f - h0 * h0, g1 = 1.0f - h1 * h1;
            float hp0 = g0 * wv.x, hp1 = g1 * wv.y;
            store_A_pair(gb, p,      k, h0, h1);
            store_A_pair(gb, 32 + p, k, hp0, hp1);
            store_A_pair(gb, 64 + p, k, -2.0f * h0 * hp0 * wv.x, -2.0f * h1 * hp1 * wv.y);
        }
    }
    __syncthreads();

    // ldmatrix lane base (x4: [m0-7,k0-7][m8-15,k0-7][m0-7,k8-15][m8-15,k8-15])
    const unsigned aA = sb + SA_HI
        + (unsigned)(wgm * 16 + ((lane >> 3) & 1) * 8 + (lane & 7)) * ROWP
        + (unsigned)((lane >> 4) << 4);

    #pragma unroll 1
    for (int l = 0; l < 2; l++) {
        ((float*)(gb + SBIAS))[tid] = (l ? b3 : b2)[tid];
        float acc[3][4][8];
        #pragma unroll
        for (int s = 0; s < 3; s++)
            #pragma unroll
            for (int nc = 0; nc < 4; nc++)
                #pragma unroll
                for (int j = 0; j < 8; j++) acc[s][nc][j] = 0.0f;

        #pragma unroll 1
        for (int nc = 0; nc < 4; nc++) {
            const uint4* pH = &g_Bf[l][0][nc][wgn][0][lane];
            const uint4* pL = &g_Bf[l][1][nc][wgn][0][lane];
            #pragma unroll
            for (int ks = 0; ks < 16; ks++) {
                uint4 bh = pH[ks * 32];
                uint4 bl = pL[ks * 32];
                unsigned ah[3][4], al[3][4];
                #pragma unroll
                for (int s = 0; s < 3; s++) {
                    unsigned ad = aA + (unsigned)(s * 32) * ROWP + (unsigned)ks * 32;
                    ldsm4(ah[s][0], ah[s][1], ah[s][2], ah[s][3], ad);
                    ldsm4(al[s][0], al[s][1], al[s][2], al[s][3], ad + (SA_LO - SA_HI));
                }
                #pragma unroll
                for (int s = 0; s < 3; s++) {
                    mma16816(acc[s][nc] + 0, ah[s], bh.x, bh.y);
                    mma16816(acc[s][nc] + 4, ah[s], bh.z, bh.w);
                }
                #pragma unroll
                for (int s = 0; s < 3; s++) {
                    mma16816(acc[s][nc] + 0, ah[s], bl.x, bl.y);
                    mma16816(acc[s][nc] + 4, ah[s], bl.z, bl.w);
                }
                #pragma unroll
                for (int s = 0; s < 3; s++) {
                    mma16816(acc[s][nc] + 0, al[s], bh.x, bh.y);
                    mma16816(acc[s][nc] + 4, al[s], bh.z, bh.w);
                }
            }
        }
        __syncthreads();   // all A reads done before epilogue overwrites A

        const float* bias = (const float*)(gb + SBIAS);
        const float* w4s  = (const float*)(gb + SW4);

        if (l == 0) {
            // tanh-chain coupling in registers; write next-layer A splits
            #pragma unroll
            for (int nc = 0; nc < 4; nc++)
                #pragma unroll
                for (int n8 = 0; n8 < 2; n8++) {
                    int n0 = nc * 64 + wgn * 16 + n8 * 8 + (lane & 3) * 2;
                    float bb0 = bias[n0], bb1 = bias[n0 + 1];
                    #pragma unroll
                    for (int rh = 0; rh < 2; rh++) {
                        int ci = n8 * 4 + rh * 2;
                        float z0 = acc[0][nc][ci] + bb0, z1 = acc[0][nc][ci + 1] + bb1;
                        float zp0 = acc[1][nc][ci],      zp1 = acc[1][nc][ci + 1];
                        float zq0 = acc[2][nc][ci],      zq1 = acc[2][nc][ci + 1];
                        float h0 = tanhf(z0), h1 = tanhf(z1);
                        float g0 = 1.0f - h0 * h0, g1 = 1.0f - h1 * h1;
                        float hp0 = g0 * zp0, hp1 = g1 * zp1;
                        float hq0 = fmaf(g0, zq0, -2.0f * h0 * hp0 * zp0);
                        float hq1 = fmaf(g1, zq1, -2.0f * h1 * hp1 * zp1);
                        int p = wgm * 16 + (lane >> 2) + rh * 8;
                        store_A_pair(gb, p,      n0, h0, h1);
                        store_A_pair(gb, 32 + p, n0, hp0, hp1);
                        store_A_pair(gb, 64 + p, n0, hq0, hq1);
                    }
                }
            __syncthreads();
        } else {
            // final tanh + W4 dot, reduced across the 4 n-group warps
            float uu[2] = {0, 0}, du_[2] = {0, 0}, dd_[2] = {0, 0};
            #pragma unroll
            for (int nc = 0; nc < 4; nc++)
                #pragma unroll
                for (int n8 = 0; n8 < 2; n8++) {
                    int n0 = nc * 64 + wgn * 16 + n8 * 8 + (lane & 3) * 2;
                    float bb0 = bias[n0], bb1 = bias[n0 + 1];
                    float w40 = w4s[n0], w41 = w4s[n0 + 1];
                    #pragma unroll
                    for (int rh = 0; rh < 2; rh++) {
                        int ci = n8 * 4 + rh * 2;
                        float z0 = acc[0][nc][ci] + bb0, z1 = acc[0][nc][ci + 1] + bb1;
                        float zp0 = acc[1][nc][ci],      zp1 = acc[1][nc][ci + 1];
                        float zq0 = acc[2][nc][ci],      zq1 = acc[2][nc][ci + 1];
                        float h0 = tanhf(z0), h1 = tanhf(z1);
                        float g0 = 1.0f - h0 * h0, g1 = 1.0f - h1 * h1;
                        float hp0 = g0 * zp0, hp1 = g1 * zp1;
                        float hq0 = fmaf(g0, zq0, -2.0f * h0 * hp0 * zp0);
                        float hq1 = fmaf(g1, zq1, -2.0f * h1 * hp1 * zp1);
                        uu[rh]  = fmaf(h0,  w40, fmaf(h1,  w41, uu[rh]));
                        du_[rh] = fmaf(hp0, w40, fmaf(hp1, w41, du_[rh]));
                        dd_[rh] = fmaf(hq0, w40, fmaf(hq1, w41, dd_[rh]));
                    }
                }
            float* dred = (float*)(gb + SDRED);
            #pragma unroll
            for (int rh = 0; rh < 2; rh++) {
                float a = uu[rh], b = du_[rh], c = dd_[rh];
                a += __shfl_xor_sync(0xffffffffu, a, 1);
                a += __shfl_xor_sync(0xffffffffu, a, 2);
                b += __shfl_xor_sync(0xffffffffu, b, 1);
                b += __shfl_xor_sync(0xffffffffu, b, 2);
                c += __shfl_xor_sync(0xffffffffu, c, 1);
                c += __shfl_xor_sync(0xffffffffu, c, 2);
                if ((lane & 3) == 0) {
                    int p = wgm * 16 + (lane >> 2) + rh * 8;
                    dred[(0 * 32 + p) * 4 + wgn] = a;
                    dred[(1 * 32 + p) * 4 + wgn] = b;
                    dred[(2 * 32 + p) * 4 + wgn] = c;
                }
            }
            __syncthreads();
            if (w < 3) {
                const float* dr = (const float*)(gb + SDRED) + (w * 32 + lane) * 4;
                float v = dr[0] + dr[1] + dr[2] + dr[3];
                int gi = gbase + lane;
                if (w == 0) {
                    v += b4v;
                    if (gi < NPTS) out[gi] = v;
                    else {
                        int qi = gi - NPTS;
                        if (qi == NQ)          g_u0 = v;
                        else if (qi == NQ + 1) g_uL = v;
                    }
                } else if (w == 1) {
                    if (gi < NPTS) out[NPTS + gi] = v;
                    else { int qi = gi - NPTS; if (qi < NQ) g_duq[qi] = v; }
                } else {
                    if (gi < NPTS) out[2 * NPTS + gi] = v;
                }
            }
        }
    }
}

// ---------------- loss reduction ----------------
__global__ void loss_kernel(float* __restrict__ out) {
    __shared__ float red[256];
    float sacc = 0.0f;
    for (int i = threadIdx.x; i < NQ; i += 256) {
        const float d = g_duq[i];
        sacc = fmaf(g_qw[i] * d, d, sacc);
    }
    red[threadIdx.x] = sacc;
    __syncthreads();
    for (int o = 128; o; o >>= 1) {
        if (threadIdx.x < o) red[threadIdx.x] += red[threadIdx.x + o];
        __syncthreads();
    }
    if (threadIdx.x == 0)
        out[3 * NPTS] = (0.5f * red[0] - 5.0f * g_uL) + g_u0 * g_u0;
}

// ---------------- launch ----------------
extern "C" void kernel_launch(void* const* d_in, const int* in_sizes, int n_in,
                              void* d_out, int out_size)
{
    (void)in_sizes; (void)n_in; (void)out_size;
    const float* x  = (const float*)d_in[0];
    const float* W1 = (const float*)d_in[1];
    const float* b1 = (const float*)d_in[2];
    const float* W2 = (const float*)d_in[3];
    const float* b2 = (const float*)d_in[4];
    const float* W3 = (const float*)d_in[5];
    const float* b3 = (const float*)d_in[6];
    const float* W4 = (const float*)d_in[7];
    const float* b4 = (const float*)d_in[8];
    float* out = (float*)d_out;

    cudaFuncSetAttribute(mlp_kernel,
                         cudaFuncAttributeMaxDynamicSharedMemorySize, SM_ALLOC);

    prep_kernel<<<128, 256>>>(W2, W3);
    mlp_kernel<<<NTILES, 256, SM_ALLOC>>>(x, W1, b1, b2, b3, W4, b4, out);
    loss_kernel<<<1, 256>>>(out);
}